// round 2
// baseline (speedup 1.0000x reference)
#include <cuda_runtime.h>
#include <math.h>

// CTC loss forward. Scaled linear-domain recursion in DOUBLE precision
// (range e^+-708 absorbs the 100-500 nat within-row spread that killed fp32),
// renormalized every RENORM_STEP steps. One block per batch element,
// 288 threads cover L = 2S+1 = 257 lattice cells, one cell per thread.
//
// alpha_new[s] = (alpha[s] + alpha[s-1] + skip[s]*alpha[s-2]) * p[t, ext[s]]
// loss = -( log(alpha_T[2tl] + alpha_T[2tl-1]) + sum log Z_k )

#define NTHR   288
#define NWARP  9
#define MAX_L2 260   // 257 cells + 2-left-pad, rounded
#define RENORM_MASK 7

// log of a positive NORMAL double via exponent split + fast float log.
__device__ __forceinline__ float fast_log_pos(double x) {
    unsigned long long b = __double_as_longlong(x);
    int ex = (int)((b >> 52) & 0x7ffull) - 1023;
    double m = __longlong_as_double((b & 0x800FFFFFFFFFFFFFull) | (1023ull << 52)); // [1,2)
    return (float)ex * 0.6931471805599453f + __logf((float)m);
}

__global__ __launch_bounds__(NTHR, 4)
void ctc_loss_kernel(const float* __restrict__ lp,     // (T, N, C) log-probs
                     const int*   __restrict__ tgt,    // (N, S)
                     const int*   __restrict__ ilen,   // (N,)
                     const int*   __restrict__ tlen,   // (N,)
                     float*       __restrict__ out,    // (N,)
                     int T, int N, int C, int S)
{
    __shared__ double bufA[MAX_L2];
    __shared__ double bufB[MAX_L2];
    __shared__ double prD[2][80];      // emission row double-buffer (exp'd)
    __shared__ double red[NWARP];

    const int n   = blockIdx.x;
    const int tid = threadIdx.x;
    const int L   = 2 * S + 1;
    const int Tn  = ilen[n];
    const long long strideT = (long long)N * C;
    const float* lpn = lp + (long long)n * C;

    // Static per-cell data.
    int  e    = 0;      // ext[s]: blank(0) even s, target odd s
    bool skip = false;
    if (tid < L && (tid & 1)) {
        e = tgt[n * S + (tid >> 1)];
        if (tid >= 3) skip = (e != tgt[n * S + (tid >> 1) - 1]);
    }

    double* acur = bufA;
    double* anxt = bufB;
    for (int i = tid; i < MAX_L2; i += NTHR) { bufA[i] = 0.0; bufB[i] = 0.0; }

    // Rows 0 and 1 exp'd into the two buffers.
    if (tid < C) {
        prD[0][tid] = (double)__expf(lpn[tid]);
        if (Tn > 1) prD[1][tid] = (double)__expf(lpn[strideT + tid]);
    }
    __syncthreads();

    // alpha0: cells 0 (blank) and 1 (first label).
    if (tid < 2) acur[tid + 2] = prD[0][e];

    // Pipeline: r_cur holds raw log-prob of row t+1 during step t (loaded in step t-1).
    float r_cur = 0.f;
    if (tid < C && 2 < Tn) r_cur = lpn[2 * strideT + tid];
    __syncthreads();   // alpha0 visible; prD[0] init reads done before step1 rewrites it

    float logZ = 0.f;
    bool  dead = false;

    for (int t = 1; t < Tn; ++t) {
        const double* pr = prD[t & 1];

        double v = 0.0;
        if (tid < L) {
            double a0 = acur[tid + 2];
            double a1 = acur[tid + 1];
            double a2 = skip ? acur[tid] : 0.0;
            v = (a0 + a1 + a2) * pr[e];
        }

        // Prefetch raw row t+2 (consumed next step) — ~1.5 steps to cover DRAM.
        float r_next = 0.f;
        if (tid < C && (t + 2) < Tn)
            r_next = lpn[(long long)(t + 2) * strideT + tid];

        if ((t & RENORM_MASK) == 0) {
            double s = v;
            #pragma unroll
            for (int o = 16; o; o >>= 1) s += __shfl_xor_sync(0xffffffffu, s, o);
            if ((tid & 31) == 0) red[tid >> 5] = s;
            __syncthreads();
            double total = 0.0;
            #pragma unroll
            for (int w = 0; w < NWARP; ++w) total += red[w];
            if (!(total > 0.0)) { dead = true; break; }   // uniform across block
            v *= (1.0 / total);
            logZ += fast_log_pos(total);                  // total never denormal
        }

        if (tid < L) anxt[tid + 2] = v;
        if (tid < C && (t + 1) < Tn)
            prD[(t + 1) & 1][tid] = (double)__expf(r_cur);
        r_cur = r_next;
        __syncthreads();   // anxt + prD visible for next step

        double* tmp = acur; acur = anxt; anxt = tmp;
    }

    if (tid == 0) {
        float loss = 0.f;
        if (!dead) {
            const int tl = tlen[n];
            double vfin = acur[2 * tl + 2] + acur[2 * tl + 1];
            if (vfin > 0.0) {
                float l = -((float)log(vfin) + logZ);    // libm log: handles denormals
                if (isfinite(l) && l < 1e10f) loss = l;
            }
        }
        out[n] = loss;
    }
}

extern "C" void kernel_launch(void* const* d_in, const int* in_sizes, int n_in,
                              void* d_out, int out_size)
{
    const float* lp   = (const float*)d_in[0];  // (T, N, C)
    const int*   tgt  = (const int*)  d_in[1];  // (N, S)
    const int*   ilen = (const int*)  d_in[2];  // (N,)
    const int*   tlen = (const int*)  d_in[3];  // (N,)
    float*       out  = (float*)d_out;

    const int N = in_sizes[2];
    const int S = in_sizes[1] / N;
    const int C = 80;
    const int T = in_sizes[0] / (N * C);

    ctc_loss_kernel<<<N, NTHR>>>(lp, tgt, ilen, tlen, out, T, N, C, S);
}

// round 4
// speedup vs baseline: 6.0532x; 6.0532x over previous
#include <cuda_runtime.h>
#include <math.h>

// CTC loss forward. Extended-range fp32 recursion: each lattice cell alpha is
// (mantissa m in [1,2) or 0, int exponent k), alpha = m * 2^k. All per-cell
// work is fp32 FMA + integer exponent surgery — no FP64 (crippled on sm_103a),
// no per-cell transcendentals, no block-wide renormalization reduction.
//
// alpha_new[s] = (alpha[s] + alpha[s-1] + skip[s]*alpha[s-2]) * p[t, ext[s]]
// loss = -( kmax*ln2 + log(msum) ) from final cells 2*tl and 2*tl-1.

#define NTHR   288
#define MAX_L2 260            // 257 cells + 2 left pad
#define KMIN   (-(1 << 26))   // exponent of dead cells (m == 0)

__device__ __forceinline__ int   f2i(float x) { return __float_as_int(x); }
__device__ __forceinline__ float i2f(int x)   { return __int_as_float(x); }

// 2^d for d <= 0; exact power of two, 0 if too small (or d hugely negative).
__device__ __forceinline__ float pow2_scale(int d) {
    return (d > -127) ? __int_as_float((127 + d) << 23) : 0.f;
}

__global__ __launch_bounds__(NTHR, 4)
void ctc_loss_kernel(const float* __restrict__ lp,     // (T, N, C) log-probs
                     const int*   __restrict__ tgt,    // (N, S)
                     const int*   __restrict__ ilen,   // (N,)
                     const int*   __restrict__ tlen,   // (N,)
                     float*       __restrict__ out,    // (N,)
                     int T, int N, int C, int S)
{
    __shared__ float2 bufA[MAX_L2];     // .x = mantissa, .y = bit-cast int exponent
    __shared__ float2 bufB[MAX_L2];
    __shared__ float  prF[2][80];       // exp'd emission rows, double-buffered

    const int n   = blockIdx.x;
    const int tid = threadIdx.x;
    const int L   = 2 * S + 1;
    const int Tn  = ilen[n];
    const long long strideT = (long long)N * C;
    const float* lpn = lp + (long long)n * C;

    // Static per-cell data.
    int  e    = 0;                      // ext[s]: blank(0) even s, target odd s
    bool skip = false;
    if (tid < L && (tid & 1)) {
        e = tgt[n * S + (tid >> 1)];
        if (tid >= 3) skip = (e != tgt[n * S + (tid >> 1) - 1]);
    }

    float2* acur = bufA;
    float2* anxt = bufB;
    const float2 deadc = make_float2(0.f, i2f(KMIN));
    for (int i = tid; i < MAX_L2; i += NTHR) { bufA[i] = deadc; bufB[i] = deadc; }

    // Emission rows 0 and 1.
    if (tid < C) {
        prF[0][tid] = __expf(lpn[tid]);
        if (Tn > 1) prF[1][tid] = __expf(lpn[strideT + tid]);
    }
    __syncthreads();

    // alpha0: cells 0 (blank) and 1 (first label): value p, split into (m, k).
    if (tid < 2) {
        float p = prF[0][e];            // p > 0 always (expf of ~N(0,1) log-softmax)
        int pb = f2i(p);
        int pe = (pb >> 23) - 127;
        float m = i2f((pb & 0x007FFFFF) | 0x3F800000);
        acur[tid + 2] = make_float2(m, i2f(pe));
    }

    // Pipeline: r_cur holds raw log-prob row t+1 during step t.
    float r_cur = 0.f;
    if (tid < C && 2 < Tn) r_cur = lpn[2 * strideT + tid];
    __syncthreads();

    for (int t = 1; t < Tn; ++t) {
        const float* pr = prF[t & 1];

        float2 c0 = acur[tid + 2];
        float2 c1 = acur[tid + 1];
        float2 c2 = acur[tid];

        int k0 = f2i(c0.y);
        int k1 = f2i(c1.y);
        int k2 = skip ? f2i(c2.y) : KMIN;
        float m2 = skip ? c2.x : 0.f;

        int km = max(k0, max(k1, k2));

        float s0 = pow2_scale(k0 - km);
        float s1 = pow2_scale(k1 - km);
        float s2 = pow2_scale(k2 - km);

        // argmax-k contributor has scale 1 and m>=1  =>  sum >= 1 unless all dead
        float sum  = fmaf(c0.x, s0, fmaf(c1.x, s1, m2 * s2));
        float prod = sum * pr[e];       // in [pr, 6*pr]: always normal fp32 if > 0

        int pb = f2i(prod);
        int pe = (pb >> 23) - 127;
        float mn = i2f((pb & 0x007FFFFF) | 0x3F800000);
        int   kn = km + pe;
        if (pb == 0) { mn = 0.f; kn = KMIN; }   // all-dead: stay exactly dead

        // Prefetch raw row t+2 (consumed next step).
        float r_next = 0.f;
        if (tid < C && (t + 2) < Tn)
            r_next = lpn[(long long)(t + 2) * strideT + tid];

        if (tid < L) anxt[tid + 2] = make_float2(mn, i2f(kn));
        if (tid < C && (t + 1) < Tn)
            prF[(t + 1) & 1][tid] = __expf(r_cur);
        r_cur = r_next;
        __syncthreads();

        float2* tmp = acur; acur = anxt; anxt = tmp;
    }

    if (tid == 0) {
        const int tl = tlen[n];
        float2 A = acur[2 * tl + 2];    // last blank
        float2 B = acur[2 * tl + 1];    // last label
        float loss = 0.f;
        if (A.x > 0.f || B.x > 0.f) {
            int ka = f2i(A.y), kb = f2i(B.y);     // dead cells carry KMIN
            int km = max(ka, kb);
            float msum = A.x * pow2_scale(ka - km) + B.x * pow2_scale(kb - km);
            float l = -((float)km * 0.69314718055994531f + __logf(msum));
            if (isfinite(l) && l < 1e10f) loss = l;
        }
        out[n] = loss;
    }
}

extern "C" void kernel_launch(void* const* d_in, const int* in_sizes, int n_in,
                              void* d_out, int out_size)
{
    const float* lp   = (const float*)d_in[0];  // (T, N, C)
    const int*   tgt  = (const int*)  d_in[1];  // (N, S)
    const int*   ilen = (const int*)  d_in[2];  // (N,)
    const int*   tlen = (const int*)  d_in[3];  // (N,)
    float*       out  = (float*)d_out;

    const int N = in_sizes[2];
    const int S = in_sizes[1] / N;
    const int C = 80;
    const int T = in_sizes[0] / (N * C);

    ctc_loss_kernel<<<N, NTHR>>>(lp, tgt, ilen, tlen, out, T, N, C, S);
}

// round 6
// speedup vs baseline: 8.9638x; 1.4808x over previous
#include <cuda_runtime.h>
#include <math.h>

// CTC loss forward — one WARP per batch element, alpha in registers.
// Extended-range fp32: cell = (mantissa m in [1,2), int exponent k), alpha = m*2^k.
// Lane l owns cells s = 8l..8l+7; lane 31 additionally owns s=256 (last blank).
// Cross-lane dependency per step: only prev lane's cell 7 (2 shuffles).
// No __syncthreads anywhere. Dead cells decay as self-killing "ghosts"
// (m=1, k -= ~|log2 p|/step from KMIN) so no dead-path selects are needed.

#define KMIN (-(1 << 26))

__device__ __forceinline__ float sc(int d) {       // 2^d for d<=0 (0 if d<=-127)
    return __int_as_float(max(d + 127, 0) << 23);
}

// 2-contributor cell (even lattice pos: blank, no skip)
__device__ __forceinline__ void cell2(float& nm, int& nk,
                                      float m0, int k0, float m1, int k1, float p) {
    int km = max(k0, k1);
    float sum  = fmaf(m0, sc(k0 - km), m1 * sc(k1 - km));
    float prod = sum * p;                          // in {0} U [p, 4p): normal or 0
    int b = __float_as_int(prod);
    nk = km + (b >> 23) - 127;
    nm = __int_as_float((b & 0x007FFFFF) | 0x3F800000);
}

// 3-contributor cell (odd lattice pos: label, optional skip)
__device__ __forceinline__ void cell3(float& nm, int& nk,
                                      float m0, int k0, float m1, int k1,
                                      float m2, int k2, float p) {
    int km = max(k0, max(k1, k2));
    float sum  = fmaf(m0, sc(k0 - km), fmaf(m1, sc(k1 - km), m2 * sc(k2 - km)));
    float prod = sum * p;
    int b = __float_as_int(prod);
    nk = km + (b >> 23) - 127;
    nm = __int_as_float((b & 0x007FFFFF) | 0x3F800000);
}

__global__ void __launch_bounds__(32)
ctc_warp_kernel(const float* __restrict__ lp,     // (T, N, C)
                const int*   __restrict__ tgt,    // (N, S)
                const int*   __restrict__ ilen,   // (N,)
                const int*   __restrict__ tlen,   // (N,)
                float*       __restrict__ out,    // (N,)
                int T, int N, int C, int S)
{
    __shared__ float buf[2][80];      // exp'd emission rows, double-buffered
    __shared__ float sm_m[257];
    __shared__ int   sm_k[257];

    const int lane = threadIdx.x;
    const int n    = blockIdx.x;
    const int Tn   = ilen[n];
    const int strideT = N * C;                       // fits int (T*N*C ~ 21M)
    const float* lpn = lp + n * C;
    const int*   tn  = tgt + n * S;

    // Static per-cell data for the 4 odd cells of this lane.
    int e1[4], sk[4];
    #pragma unroll
    for (int q = 0; q < 4; ++q) {
        int s  = 8 * lane + 2 * q + 1;
        int ei = tn[s >> 1];
        e1[q] = ei;
        sk[q] = (s >= 3 && ei != tn[(s >> 1) - 1]) ? 1 : 0;
    }

    float m[9]; int k[9];
    #pragma unroll
    for (int j = 0; j < 9; ++j) { m[j] = 0.f; k[j] = KMIN; }

    // ---- emission helpers: 80 floats spread over 32 lanes (lane, +32, +64<80) ----
    auto ld3 = [&](int t, float r[3]) {
        if (t < Tn) {
            const float* p = lpn + t * strideT;
            r[0] = p[lane];
            r[1] = p[lane + 32];
            r[2] = (lane < 16) ? p[lane + 64] : 0.f;
        }
    };
    auto ex3 = [&](const float r[3], float er[3]) {
        er[0] = __expf(r[0]); er[1] = __expf(r[1]); er[2] = __expf(r[2]);
    };
    auto st3 = [&](int b, const float er[3]) {
        buf[b][lane]      = er[0];
        buf[b][lane + 32] = er[1];
        if (lane < 16) buf[b][lane + 64] = er[2];
    };

    // ---- prologue: rows 0..5 (Tn >= T/2 = 256 always; loads guarded anyway) ----
    float ra[3], rb[3], ea[3], eb[3], eE[3], rw0[3], rw1[3], rw2[3];
    ld3(0, ra);  ld3(1, rb);
    ex3(ra, ea); ex3(rb, eb);
    st3(0, ea);  st3(1, eb);
    ld3(2, ra);                   // row 2 raw
    ld3(3, rw0); ld3(4, rw1); ld3(5, rw2);
    __syncwarp();

    if (lane == 0) {              // alpha0: cells 0 (blank) and 1 (first label)
        float p0 = buf[0][0];
        int b = __float_as_int(p0);
        k[0] = (b >> 23) - 127;
        m[0] = __int_as_float((b & 0x007FFFFF) | 0x3F800000);
        float p1 = buf[0][e1[0]];
        b = __float_as_int(p1);
        k[1] = (b >> 23) - 127;
        m[1] = __int_as_float((b & 0x007FFFFF) | 0x3F800000);
    }
    ex3(ra, eE);                  // eE = exp'd row 2

    // ---- main recursion: step t applies emission row t ----
    // invariants at top of iter t: buf[t&1]=row t, eE=row t+1,
    // rw0=raw t+2, rw1=raw t+3, rw2=raw t+4
    #pragma unroll 2
    for (int t = 1; t < Tn; ++t) {
        __syncwarp();                       // orders prev-step gathers vs this STS
        const int bc = t & 1;
        st3(bc ^ 1, eE);                    // stage row t+1 (disjoint buffer)

        float pb = buf[bc][0];              // blank prob (broadcast)
        float p1 = buf[bc][e1[0]];
        float p3 = buf[bc][e1[1]];
        float p5 = buf[bc][e1[2]];
        float p7 = buf[bc][e1[3]];

        float m7p = __shfl_up_sync(0xffffffffu, m[7], 1);
        int   k7p = __shfl_up_sync(0xffffffffu, k[7], 1);
        if (lane == 0) k7p = KMIN;          // cell -1 is dead

        float nm[9]; int nk[9];
        cell2(nm[0], nk[0], m[0], k[0], m7p, k7p, pb);
        cell3(nm[1], nk[1], m[1], k[1], m[0], k[0], m7p,  sk[0] ? k7p  : KMIN, p1);
        cell2(nm[2], nk[2], m[2], k[2], m[1], k[1], pb);
        cell3(nm[3], nk[3], m[3], k[3], m[2], k[2], m[1], sk[1] ? k[1] : KMIN, p3);
        cell2(nm[4], nk[4], m[4], k[4], m[3], k[3], pb);
        cell3(nm[5], nk[5], m[5], k[5], m[4], k[4], m[3], sk[2] ? k[3] : KMIN, p5);
        cell2(nm[6], nk[6], m[6], k[6], m[5], k[5], pb);
        cell3(nm[7], nk[7], m[7], k[7], m[6], k[6], m[5], sk[3] ? k[5] : KMIN, p7);
        cell2(nm[8], nk[8], m[8], k[8], m[7], k[7], pb);   // shadow of next lane's cell 0
        #pragma unroll
        for (int j = 0; j < 9; ++j) { m[j] = nm[j]; k[j] = nk[j]; }

        // advance emission pipeline (3-step LDG lead covers DRAM latency)
        ex3(rw0, eE);                       // row t+2 for next iter's STS
        #pragma unroll
        for (int i = 0; i < 3; ++i) { rw0[i] = rw1[i]; rw1[i] = rw2[i]; }
        ld3(t + 5, rw2);
    }

    // ---- readout ----
    __syncwarp();
    #pragma unroll
    for (int j = 0; j < 8; ++j) {
        sm_m[8 * lane + j] = m[j];
        sm_k[8 * lane + j] = k[j];
    }
    if (lane == 31) { sm_m[256] = m[8]; sm_k[256] = k[8]; }
    __syncwarp();

    if (lane == 0) {
        const int tl = tlen[n];
        const int ia = 2 * tl, ib = 2 * tl - 1;
        float mA = sm_m[ia]; int kA = sm_k[ia];
        float mB = sm_m[ib]; int kB = sm_k[ib];
        int   km = max(kA, kB);
        float msum = mA * sc(kA - km) + mB * sc(kB - km);
        float loss = 0.f;
        if (msum > 0.f && km > -(1 << 25)) {    // km guard rejects ghost-only readout
            float l = -0.69314718055994531f * ((float)km + __log2f(msum));
            if (isfinite(l) && l < 1e10f) loss = l;
        }
        out[n] = loss;
    }
}

extern "C" void kernel_launch(void* const* d_in, const int* in_sizes, int n_in,
                              void* d_out, int out_size)
{
    const float* lp   = (const float*)d_in[0];  // (T, N, C)
    const int*   tgt  = (const int*)  d_in[1];  // (N, S)
    const int*   ilen = (const int*)  d_in[2];  // (N,)
    const int*   tlen = (const int*)  d_in[3];  // (N,)
    float*       out  = (float*)d_out;

    const int N = in_sizes[2];
    const int S = in_sizes[1] / N;
    const int C = 80;
    const int T = in_sizes[0] / (N * C);

    ctc_warp_kernel<<<N, 32>>>(lp, tgt, ilen, tlen, out, T, N, C, S);
}